// round 4
// baseline (speedup 1.0000x reference)
#include <cuda_runtime.h>
#include <cuda_bf16.h>

// AngleTensor: out[b,i,j,k] = mask * arccos( u_ij . u_ik ),  u_ij = (p_j-p_i)/d_ij
// B=8, N=128 fixed. Exploits j<->k symmetry: the 128x128 (j,k) matrix per (b,i)
// is split into 32x32 tiles; only the 10 unique tiles (4 diag + 6 upper) are
// computed. Off-diagonal tiles are mirrored into the transposed position via a
// padded shared-memory stage (STS scatter -> LDS -> coalesced float4 STG).
//
// grid = (10 tile-pairs, N, B), 128 threads/block.
// Thread layout inside a 32x32 tile: warp w owns rows [8w, 8w+8);
// lane l: rows rA = 8w+(l>>3), rB = rA+4; cols cv = 4*(l&7) .. +3  (8 elems).
// Direct store: 2x STG.128, fully coalesced.
// acos via A&S 4.4.45 (abs err 6.7e-5 rad). Mask folded via z in sh[].w.

#define N_FIXED 128
#define PI_F 3.14159265358979f

__device__ __forceinline__ float acos_approx(float c) {
    const float x = fabsf(c);
    const float y = fmaxf(1.0f - x, 1e-12f);   // also kills NaN
    const float s = y * rsqrtf(y);             // sqrt(y)
    float p = fmaf(x, -0.0187293f, 0.0742610f);
    p = fmaf(p, x, -0.2121144f);
    p = fmaf(p, x, 1.5707288f);
    const float bb = s * p;
    return (c < 0.0f) ? (PI_F - bb) : bb;
}

__constant__ int TJ_TBL[10] = {0, 1, 2, 3, 0, 0, 0, 1, 1, 2};
__constant__ int TK_TBL[10] = {0, 1, 2, 3, 1, 2, 3, 2, 3, 3};

__global__ __launch_bounds__(128) void angle_kernel(
    const float* __restrict__ pos,   // (B, N, 3)
    const float* __restrict__ dist,  // (B, N, N)
    float* __restrict__ out)         // (B, N, N, N)
{
    const int tp = blockIdx.x;       // 0..9 unique tile pair
    const int i  = blockIdx.y;
    const int b  = blockIdx.z;
    const int N  = N_FIXED;

    const int tj = TJ_TBL[tp];
    const int tk = TK_TBL[tp];

    __shared__ float4 sh[N_FIXED];       // unit vectors + mask flag
    __shared__ float  tileS[32 * 33];    // transpose stage (pad 33: conflict-free)

    const float pix = pos[(b * N + i) * 3 + 0];
    const float piy = pos[(b * N + i) * 3 + 1];
    const float piz = pos[(b * N + i) * 3 + 2];

    {
        const int j = threadIdx.x;
        const float px = pos[(b * N + j) * 3 + 0];
        const float py = pos[(b * N + j) * 3 + 1];
        const float pz = pos[(b * N + j) * 3 + 2];
        const float d  = dist[((size_t)b * N + i) * N + j];
        const float inv = (d > 0.0f) ? (1.0f / d) : 0.0f;  // zero vec on masked row
        const float zz  = (j != i && d > 0.0f) ? 1.0f : 0.0f;
        sh[j] = make_float4((px - pix) * inv, (py - piy) * inv, (pz - piz) * inv, zz);
    }
    __syncthreads();

    const int t = threadIdx.x;
    const int w = t >> 5;
    const int l = t & 31;

    const int rA = w * 8 + (l >> 3);     // row (within tile) for first group
    const int rB = rA + 4;               // second group
    const int cv = (l & 7) * 4;          // first of 4 cols (within tile)

    const int j0 = tj * 32 + rA;
    const int j1 = tj * 32 + rB;
    const int kc = tk * 32 + cv;

    const float4 uj0 = sh[j0];
    const float4 uj1 = sh[j1];
    const float4 uk0 = sh[kc + 0];
    const float4 uk1 = sh[kc + 1];
    const float4 uk2 = sh[kc + 2];
    const float4 uk3 = sh[kc + 3];

    float va[4], vb[4];

    {
        const float c0 = uj0.x * uk0.x + uj0.y * uk0.y + uj0.z * uk0.z;
        const float c1 = uj0.x * uk1.x + uj0.y * uk1.y + uj0.z * uk1.z;
        const float c2 = uj0.x * uk2.x + uj0.y * uk2.y + uj0.z * uk2.z;
        const float c3 = uj0.x * uk3.x + uj0.y * uk3.y + uj0.z * uk3.z;
        va[0] = acos_approx(c0) * (uj0.w * uk0.w);
        va[1] = acos_approx(c1) * (uj0.w * uk1.w);
        va[2] = acos_approx(c2) * (uj0.w * uk2.w);
        va[3] = acos_approx(c3) * (uj0.w * uk3.w);

        const float d0 = uj1.x * uk0.x + uj1.y * uk0.y + uj1.z * uk0.z;
        const float d1 = uj1.x * uk1.x + uj1.y * uk1.y + uj1.z * uk1.z;
        const float d2 = uj1.x * uk2.x + uj1.y * uk2.y + uj1.z * uk2.z;
        const float d3 = uj1.x * uk3.x + uj1.y * uk3.y + uj1.z * uk3.z;
        vb[0] = acos_approx(d0) * (uj1.w * uk0.w);
        vb[1] = acos_approx(d1) * (uj1.w * uk1.w);
        vb[2] = acos_approx(d2) * (uj1.w * uk2.w);
        vb[3] = acos_approx(d3) * (uj1.w * uk3.w);
    }

    if (tj == tk) {
        // zero the j==k diagonal (r == c within the tile)
#pragma unroll
        for (int m = 0; m < 4; m++) {
            if (rA == cv + m) va[m] = 0.0f;
            if (rB == cv + m) vb[m] = 0.0f;
        }
    }

    float* obase = out + (((size_t)b * N + i) * N) * N;

    // direct (coalesced) store of tile (tj, tk)
    {
        float4 s0 = make_float4(va[0], va[1], va[2], va[3]);
        float4 s1 = make_float4(vb[0], vb[1], vb[2], vb[3]);
        *reinterpret_cast<float4*>(obase + (size_t)j0 * N + kc) = s0;
        *reinterpret_cast<float4*>(obase + (size_t)j1 * N + kc) = s1;
    }

    if (tj != tk) {
        // stage transposed: tileS[c*33 + r] = A[r][c]   (conflict-free scatter)
#pragma unroll
        for (int m = 0; m < 4; m++) {
            tileS[(cv + m) * 33 + rA] = va[m];
            tileS[(cv + m) * 33 + rB] = vb[m];
        }
        __syncthreads();

        // read back rows of the transpose: T[r][c] = A[c][r] = tileS[r*33 + c]
        float4 ta, tb;
        ta.x = tileS[rA * 33 + cv + 0];
        ta.y = tileS[rA * 33 + cv + 1];
        ta.z = tileS[rA * 33 + cv + 2];
        ta.w = tileS[rA * 33 + cv + 3];
        tb.x = tileS[rB * 33 + cv + 0];
        tb.y = tileS[rB * 33 + cv + 1];
        tb.z = tileS[rB * 33 + cv + 2];
        tb.w = tileS[rB * 33 + cv + 3];

        const int k0m = tk * 32 + rA;    // mirror rows (k index)
        const int k1m = tk * 32 + rB;
        const int jcm = tj * 32 + cv;    // mirror cols (j index)
        *reinterpret_cast<float4*>(obase + (size_t)k0m * N + jcm) = ta;
        *reinterpret_cast<float4*>(obase + (size_t)k1m * N + jcm) = tb;
    }
}

extern "C" void kernel_launch(void* const* d_in, const int* in_sizes, int n_in,
                              void* d_out, int out_size) {
    const float* pos  = (const float*)d_in[0];   // positions (B, N, 3)
    const float* dist = (const float*)d_in[1];   // dist_matrix (B, N, N)
    float* out = (float*)d_out;                  // (B, N, N, N) fp32

    const int N = (int)(3LL * in_sizes[1] / in_sizes[0]);   // = 128
    const int B = in_sizes[0] / (3 * N);                    // = 8

    dim3 grid(10, N, B);
    angle_kernel<<<grid, 128>>>(pos, dist, out);
}